// round 2
// baseline (speedup 1.0000x reference)
#include <cuda_runtime.h>

#define NWARM 365

// PARAM_RANGES lo/hi, order: KC,PCTIM,ADIMP,UZTWM,UZFWM,LZTWM,LZFSM,LZFPM,RSERV,
// PFREE,RIVA,ZPERC,REXP,UZK,LZSK,LZPK,CI,CGS,CGP,KE,XE
__constant__ float c_lo[21] = {0.1f, 0.0f, 0.0f, 10.0f, 10.0f, 50.0f, 10.0f, 50.0f,
                               0.0f, 0.0f, 0.0f, 5.0f, 1.0f, 0.1f, 0.01f, 0.001f,
                               0.5f, 0.95f, 0.98f, 0.0f, 0.0f};
__constant__ float c_hi[21] = {1.2f, 0.1f, 0.3f, 100.0f, 100.0f, 400.0f, 100.0f, 1000.0f,
                               0.3f, 0.5f, 0.1f, 350.0f, 4.0f, 0.5f, 0.35f, 0.05f,
                               0.9f, 0.998f, 0.998f, 1.0f, 0.5f};

__global__ void __launch_bounds__(128, 1) sac_kernel(
    const float2* __restrict__ pe,      // [T, B] of (prcp, pet)
    const float*  __restrict__ raw,     // [B, 21] raw params in [0.01, 0.99]
    float*        __restrict__ out,     // [2, T-NWARM, B]
    int T, int B)
{
    int b = blockIdx.x * blockDim.x + threadIdx.x;
    if (b >= B) return;

    // ---- load + scale parameters (one-time, uncoalesced is fine) ----
    float pr[21];
#pragma unroll
    for (int i = 0; i < 21; ++i)
        pr[i] = fmaf(raw[b * 21 + i], c_hi[i] - c_lo[i], c_lo[i]);

    const float kc = pr[0],  pctim = pr[1],  adimp = pr[2];
    const float uztwm = pr[3], uzfwm = pr[4], lztwm = pr[5];
    const float lzfsm = pr[6], lzfpm = pr[7];
    const float pfree = pr[9], riva = pr[10];
    const float zperc = pr[11], rexp = pr[12], uzk = pr[13];
    const float lzsk = pr[14], lzpk = pr[15];
    const float ci = pr[16], cgs = pr[17], cgp = pr[18];
    const float ke = pr[19], xe = pr[20];

    // ---- precompute all parameter-only reciprocals / combos ----
    const float inv_uztwm    = 1.0f / uztwm;
    const float inv_sum_utlt = 1.0f / (uztwm + lztwm);
    const float inv_lztwm    = 1.0f / lztwm;
    const float sum_uzm      = uztwm + uzfwm;
    const float inv_uzfwm    = 1.0f / uzfwm;
    const float pbase        = lzfsm * lzsk + lzfpm * lzpk;
    const float sum_lzm      = lzfsm + lzfpm + lztwm;
    const float inv_sum_lzm  = 1.0f / sum_lzm;
    const float sum_lzf      = lzfsm + lzfpm;
    const float cf           = lzfpm / sum_lzf;
    const float inv_lzfpm    = 1.0f / lzfpm;
    const float inv_lzfsm    = 1.0f / lzfsm;
    const float parea        = 1.0f - pctim - adimp;
    const float omci  = 1.0f - ci;
    const float omcgs = 1.0f - cgs;
    const float omcgp = 1.0f - cgp;
    const float dtm   = 0.5f;                    // 0.5 * HYDRODT
    const float denom = ke * (1.0f - xe) + dtm;
    const float inv_denom = 1.0f / denom;
    const float c1 = (ke * xe + dtm) * inv_denom;
    const float c2 = (dtm - ke * xe) * inv_denom;
    const float c3 = (ke * (1.0f - xe) - dtm) * inv_denom;

    // ---- state, all init to 0.01 ----
    float auztw = 0.01f, alztw = 0.01f, uztw = 0.01f, uzfw = 0.01f, lztw = 0.01f;
    float lzfs = 0.01f, lzfp = 0.01f;
    float qs = 0.01f, qi = 0.01f, qgs = 0.01f, qgp = 0.01f, mq = 0.01f;

    const int TOUT = T - NWARM;
    float* __restrict__ outQ = out;                       // [TOUT, B]
    float* __restrict__ outE = out + (size_t)TOUT * B;    // [TOUT, B]

    float2 cur = pe[b];  // t = 0
    for (int t = 0; t < T; ++t) {
        // software prefetch: pull next timestep's load off the critical path
        float2 nxt = (t + 1 < T) ? pe[(size_t)(t + 1) * B + b] : cur;

        float p = fmaxf(cur.x, 0.0f);
        float e = cur.y;
        if (!isfinite(e)) e = 0.0f;        // nan_to_num(nan/±inf -> 0)
        e = fmaxf(e, 0.0f);
        float ep = kc * e;

        float roimp = pctim * p;
        float ae2 = pctim * ep;
        float ae1 = fminf(auztw, ep * (auztw * inv_uztwm));
        float ae3 = fmaxf((ep - ae1) * (alztw * inv_sum_utlt), 0.0f);
        float pav = fmaxf(p - (uztwm - (auztw - ae1)), 0.0f);
        float adsur = fmaxf(pav * ((alztw - ae3) * inv_lztwm), 0.0f);
        float tmpA = pav - adsur + (alztw - ae3);
        float ars = fmaxf(tmpA - lztwm, 0.0f);
        auztw = fmaxf(fminf(uztwm, auztw - ae1 + p), 0.0f);
        alztw = fmaxf(fminf(lztwm, tmpA), 0.0f);

        float e1 = fminf(uztw, ep * (uztw * inv_uztwm));
        float e2 = fmaxf(fminf(uzfw, ep - e1), 0.0f);
        float e3 = fmaxf((ep - e1 - e2) * (lztw * inv_sum_utlt), 0.0f);
        float lt1 = fmaxf(lztw - e3, 0.0f);
        float e4 = riva * ep;
        float et = ae2 + ae1 + ae3 + e1 + e2 + e3 + e4;

        float x = p + (uztw + uzfw - e1 - e2);
        float rs = fmaxf(x - sum_uzm, 0.0f) * parea;
        float ut = fmaxf(fminf(uztwm, uztw - e1 + p), 0.0f);
        float uf = fmaxf(fminf(uzfwm, x - ut), 0.0f);
        float ri = uf * uzk;
        uf = fmaxf(uf - ri, 0.0f);

        float ss = lzfs + lzfp + lt1;
        float defr = fmaxf(1.0f - ss * inv_sum_lzm, 0.0f);
        float perc = pbase * (1.0f + zperc * __powf(defr, rexp)) * uf * inv_uzfwm;
        float rate = fmaxf(fminf(perc, sum_lzm - ss), 0.0f);
        uf = fmaxf(uf - rate, 0.0f);

        float fx = fmaxf(fminf(sum_lzf - (lzfs + lzfp),
                               fmaxf(rate - (lztwm - lt1), rate * pfree)), 0.0f);
        float perct = rate - fx;
        float ca = 1.0f - lzfp * inv_lzfpm;
        float cb = 1.0f - lzfs * inv_lzfsm;
        float coef = fminf(cf * __fdividef(2.0f * ca, ca + cb), 1.0f);
        float percp = fmaxf(fminf(lzfpm - lzfp,
                                  fmaxf(fx - (lzfsm - lzfs), coef * fx)), 0.0f);
        float percs = fmaxf(fx - percp, 0.0f);

        float lt = fminf(lt1 + perct, lztwm);
        float ls = lzfs + percs;
        float lp = lzfp + percp;
        float rgs = ls * lzsk;
        ls = fmaxf(ls - rgs, 0.0f);
        float rgp = lp * lzpk;
        lp = fmaxf(lp - rgp, 0.0f);

        float rs_tot = roimp + adsur * adimp + ars * adimp + rs;
        float i1 = qs + qi + qgs + qgp;
        qs  = rs_tot;
        qi  = ci  * qi  + omci  * (ri  * parea);
        qgs = cgs * qgs + omcgs * (rgs * parea);
        qgp = cgp * qgp + omcgp * (rgp * parea);
        float i2 = qs + qi + qgs + qgp;
        float o2 = c1 * i1 + c2 * i2 + c3 * mq;
        mq = o2;

        uztw = ut; uzfw = uf; lztw = lt; lzfs = ls; lzfp = lp;

        if (t >= NWARM) {
            int to = t - NWARM;
            outQ[(size_t)to * B + b] = o2;
            outE[(size_t)to * B + b] = et;
        }
        cur = nxt;
    }
}

extern "C" void kernel_launch(void* const* d_in, const int* in_sizes, int n_in,
                              void* d_out, int out_size) {
    const float* pe     = (const float*)d_in[0];   // [T, B, 2] f32
    const float* params = (const float*)d_in[1];   // [B, 21]  f32
    int B = in_sizes[1] / 21;
    int T = in_sizes[0] / (2 * B);
    int threads = 128;
    int blocks = (B + threads - 1) / threads;
    sac_kernel<<<blocks, threads>>>((const float2*)pe, params, (float*)d_out, T, B);
}